// round 2
// baseline (speedup 1.0000x reference)
#include <cuda_runtime.h>
#include <math.h>

// ---------------- problem constants ----------------
#define Bn   2
#define Ln   1024
#define Tn   2048      // B*L tokens
#define Dm   1024
#define Em   2048
#define Vv   32000
#define Sn   16
#define Rn   64
#define Kc   4
#define NLn  4
#define RS2  96        // R + 2S

// ---------------- scratch (static device memory; no allocs) ----------------
static const size_t OFF_H     = 0;
static const size_t OFF_XN    = OFF_H     + (size_t)Tn*Dm;
static const size_t OFF_UZ    = OFF_XN    + (size_t)Tn*Dm;
static const size_t OFF_U     = OFF_UZ    + (size_t)Tn*2*Em;
static const size_t OFF_DBC   = OFF_U     + (size_t)Tn*Em;
static const size_t OFF_PART  = OFF_DBC   + (size_t)Tn*RS2;
static const size_t OFF_DELTA = OFF_PART  + (size_t)8*Tn*RS2;
static const size_t OFF_Y     = OFF_DELTA + (size_t)Tn*Em;
static const size_t OFF_WBAR  = OFF_Y     + (size_t)Tn*Em;
static const size_t OFF_BSUM  = OFF_WBAR  + (size_t)Dm;
static const size_t SCRATCH_TOTAL = OFF_BSUM + 16;

__device__ __align__(16) float g_scratch[SCRATCH_TOTAL];

// ---------------- helpers ----------------
__device__ __forceinline__ float block_reduce_sum(float v, float* sbuf) {
    #pragma unroll
    for (int o = 16; o; o >>= 1) v += __shfl_xor_sync(0xffffffffu, v, o);
    int w = threadIdx.x >> 5, ln = threadIdx.x & 31;
    if (ln == 0) sbuf[w] = v;
    __syncthreads();
    if (threadIdx.x < 32) {
        v = (threadIdx.x < (blockDim.x >> 5)) ? sbuf[threadIdx.x] : 0.f;
        #pragma unroll
        for (int o = 4; o; o >>= 1) v += __shfl_xor_sync(0xffffffffu, v, o);
        if (threadIdx.x == 0) sbuf[0] = v;
    }
    __syncthreads();
    float r = sbuf[0];
    __syncthreads();
    return r;
}

__device__ __forceinline__ float silu_f(float z) {
    return z / (1.f + __expf(-z));
}

// ---------------- embedding gather ----------------
__global__ void embed_kernel(const int* __restrict__ x, const float* __restrict__ mask,
                             const float* __restrict__ emb, float* __restrict__ h) {
    int t = blockIdx.x;
    int tid = threadIdx.x;           // 256 threads, 1 float4 each (D=1024)
    int tok = x[t];
    float m = mask[t];
    float4 v = *(const float4*)(emb + (size_t)tok * Dm + tid * 4);
    v.x *= m; v.y *= m; v.z *= m; v.w *= m;
    *(float4*)(h + (size_t)t * Dm + tid * 4) = v;
}

// ---------------- RMSNorm ----------------
__global__ void rmsnorm_kernel(const float* __restrict__ h, const float* __restrict__ nw,
                               float* __restrict__ xn) {
    __shared__ float sb[32];
    int t = blockIdx.x, tid = threadIdx.x;
    float4 v = *(const float4*)(h + (size_t)t * Dm + tid * 4);
    float ss = v.x*v.x + v.y*v.y + v.z*v.z + v.w*v.w;
    ss = block_reduce_sum(ss, sb);
    float sc = rsqrtf(ss * (1.f / Dm) + 1e-5f);
    float4 w = *(const float4*)(nw + tid * 4);
    v.x = v.x * sc * w.x; v.y = v.y * sc * w.y;
    v.z = v.z * sc * w.z; v.w = v.w * sc * w.w;
    *(float4*)(xn + (size_t)t * Dm + tid * 4) = v;
}

// ---------------- generic SGEMM: C[MxN] = A[MxK] * B[KxN] ----------------
// epi 0: store; epi 1: softplus(acc + bias[n]); epi 2: C += acc (residual)
// requires: M % 128 == 0, K % 8 == 0, N % 4 == 0, lda/ldb % 4 == 0
__global__ void sgemm_kernel(const float* __restrict__ A, const float* __restrict__ B,
                             float* __restrict__ C, int M, int N, int Kd,
                             int lda, int ldb, int ldc,
                             const float* __restrict__ bias, int epi) {
    __shared__ float As[8][128];
    __shared__ float Bs[8][128];
    const int tid = threadIdx.x;
    const int bm = blockIdx.y * 128;
    const int bn = blockIdx.x * 128;
    const int tx = tid & 15;
    const int ty = tid >> 4;
    const int arow = tid >> 1;
    const int acol = (tid & 1) << 2;
    const int brow = tid >> 5;
    const int bcol = (tid & 31) << 2;

    float acc[8][8];
    #pragma unroll
    for (int i = 0; i < 8; i++)
        #pragma unroll
        for (int j = 0; j < 8; j++) acc[i][j] = 0.f;

    const float* Ap = A + (size_t)(bm + arow) * lda + acol;
    const float* Bp = B + (size_t)brow * ldb + bn + bcol;
    const bool bvalid = (bn + bcol) < N;

    for (int k0 = 0; k0 < Kd; k0 += 8) {
        float4 av = *(const float4*)(Ap + k0);
        As[acol + 0][arow] = av.x;
        As[acol + 1][arow] = av.y;
        As[acol + 2][arow] = av.z;
        As[acol + 3][arow] = av.w;
        float4 bv = make_float4(0.f, 0.f, 0.f, 0.f);
        if (bvalid) bv = *(const float4*)(Bp + (size_t)k0 * ldb);
        *(float4*)&Bs[brow][bcol] = bv;
        __syncthreads();
        #pragma unroll
        for (int kk = 0; kk < 8; kk++) {
            float a[8], b[8];
            *(float4*)&a[0] = *(const float4*)&As[kk][ty << 3];
            *(float4*)&a[4] = *(const float4*)&As[kk][(ty << 3) + 4];
            *(float4*)&b[0] = *(const float4*)&Bs[kk][tx << 3];
            *(float4*)&b[4] = *(const float4*)&Bs[kk][(tx << 3) + 4];
            #pragma unroll
            for (int i = 0; i < 8; i++)
                #pragma unroll
                for (int j = 0; j < 8; j++)
                    acc[i][j] = fmaf(a[i], b[j], acc[i][j]);
        }
        __syncthreads();
    }
    #pragma unroll
    for (int i = 0; i < 8; i++) {
        int row = bm + (ty << 3) + i;
        #pragma unroll
        for (int j = 0; j < 8; j++) {
            int col = bn + (tx << 3) + j;
            if (col < N) {
                float v = acc[i][j];
                if (epi == 1) {
                    v += bias[col];
                    v = (v > 15.f) ? v : log1pf(__expf(v));
                } else if (epi == 2) {
                    v += C[(size_t)row * ldc + col];
                }
                C[(size_t)row * ldc + col] = v;
            }
        }
    }
}

// ---------------- causal depthwise conv (K=4) + SiLU ----------------
__global__ void conv_silu_kernel(const float* __restrict__ uz, const float* __restrict__ cw,
                                 const float* __restrict__ cb, float* __restrict__ u) {
    int idx = blockIdx.x * blockDim.x + threadIdx.x;  // over T*E
    int e = idx & (Em - 1);
    int t = idx >> 11;
    int l = t & (Ln - 1);
    float acc = cb[e];
    #pragma unroll
    for (int k = 0; k < Kc; k++) {
        int li = l - (Kc - 1) + k;
        if (li >= 0)
            acc = fmaf(uz[(size_t)(t - (Kc - 1) + k) * (2 * Em) + e], cw[e * Kc + k], acc);
    }
    u[idx] = silu_f(acc);
}

// ---------------- dbc = u @ W_x   (tall-skinny, split-K) ----------------
__global__ void dbc_gemm_kernel(const float* __restrict__ U, const float* __restrict__ Wx,
                                float* __restrict__ part) {
    __shared__ float su[32][33];
    const int n = threadIdx.x;           // 0..95
    const int t0 = blockIdx.x * 32;
    const int k0 = blockIdx.y * (Em / 8);
    float acc[32];
    #pragma unroll
    for (int t = 0; t < 32; t++) acc[t] = 0.f;

    for (int kc = 0; kc < Em / 8; kc += 32) {
        for (int i = n; i < 32 * 32; i += 96) {
            int t = i >> 5, kk = i & 31;
            su[t][kk] = U[(size_t)(t0 + t) * Em + k0 + kc + kk];
        }
        __syncthreads();
        for (int kk = 0; kk < 32; kk++) {
            float w = Wx[(size_t)(k0 + kc + kk) * RS2 + n];
            #pragma unroll
            for (int t = 0; t < 32; t++)
                acc[t] = fmaf(su[t][kk], w, acc[t]);
        }
        __syncthreads();
    }
    #pragma unroll
    for (int t = 0; t < 32; t++)
        part[((size_t)blockIdx.y * Tn + (t0 + t)) * RS2 + n] = acc[t];
}

__global__ void dbc_reduce_kernel(const float* __restrict__ part, float* __restrict__ dbc) {
    int idx = blockIdx.x * blockDim.x + threadIdx.x;  // over T*96
    float s = 0.f;
    #pragma unroll
    for (int j = 0; j < 8; j++) s += part[(size_t)j * Tn * RS2 + idx];
    dbc[idx] = s;
}

// ---------------- selective scan ----------------
// one thread per (b, e, s); 16-lane shfl reduction over s each step
__global__ void scan_kernel(const float* __restrict__ delta, const float* __restrict__ u,
                            const float* __restrict__ dbc, const float* __restrict__ A_log,
                            const float* __restrict__ Dskip, float* __restrict__ y) {
    int tid = blockIdx.x * blockDim.x + threadIdx.x;  // B*E*S = 65536
    int s = tid & (Sn - 1);
    int e = (tid >> 4) & (Em - 1);
    int b = tid >> 15;
    float Aes = -__expf(A_log[e * Sn + s]);
    float dsk = Dskip[e];
    float h = 0.f;
    int t = b * Ln;
    for (int l = 0; l < Ln; l++, t++) {
        float dlt = delta[(size_t)t * Em + e];
        float uu  = u[(size_t)t * Em + e];
        float Bv  = dbc[(size_t)t * RS2 + Rn + s];
        float Cv  = dbc[(size_t)t * RS2 + Rn + Sn + s];
        float dA = __expf(dlt * Aes);
        h = fmaf(dA, h, dlt * uu * Bv);
        float c = h * Cv;
        c += __shfl_xor_sync(0xffffffffu, c, 1);
        c += __shfl_xor_sync(0xffffffffu, c, 2);
        c += __shfl_xor_sync(0xffffffffu, c, 4);
        c += __shfl_xor_sync(0xffffffffu, c, 8);
        if (s == 0) y[(size_t)t * Em + e] = fmaf(uu, dsk, c);
    }
}

// ---------------- gated = y * silu(z) ----------------
__global__ void gated_kernel(const float* __restrict__ uz, float* __restrict__ y) {
    int idx = blockIdx.x * blockDim.x + threadIdx.x;  // over T*E
    int e = idx & (Em - 1);
    int t = idx >> 11;
    float z = uz[(size_t)t * (2 * Em) + Em + e];
    y[idx] *= silu_f(z);
}

// ---------------- rw mean scale (folded GEMM) ----------------
__global__ void wbar_kernel(const float* __restrict__ Wrw, const float* __restrict__ brw,
                            float* __restrict__ wbar, float* __restrict__ bsum) {
    int d = blockIdx.x * blockDim.x + threadIdx.x;
    if (d < Dm) {
        float s = 0.f;
        #pragma unroll
        for (int j = 0; j < Sn; j++) s += Wrw[(size_t)d * Sn + j];
        wbar[d] = s;
    }
    if (d == 0) {
        float s = 0.f;
        #pragma unroll
        for (int j = 0; j < Sn; j++) s += brw[j];
        *bsum = s;
    }
}

__global__ void rwscale_kernel(float* __restrict__ h, const float* __restrict__ wbar,
                               const float* __restrict__ bsum) {
    __shared__ float sb[32];
    int t = blockIdx.x, tid = threadIdx.x;
    float4 v = *(const float4*)(h + (size_t)t * Dm + tid * 4);
    float4 w = *(const float4*)(wbar + tid * 4);
    float dot = v.x * w.x + v.y * w.y + v.z * w.z + v.w * w.w;
    dot = block_reduce_sum(dot, sb);
    float val = (dot + *bsum) * (1.f / Sn);
    v.x *= val; v.y *= val; v.z *= val; v.w *= val;
    *(float4*)(h + (size_t)t * Dm + tid * 4) = v;
}

// ---------------- final LayerNorm ----------------
__global__ void layernorm_kernel(const float* __restrict__ h, const float* __restrict__ g,
                                 const float* __restrict__ bta, float* __restrict__ out) {
    __shared__ float sb[32];
    int t = blockIdx.x, tid = threadIdx.x;
    float4 v = *(const float4*)(h + (size_t)t * Dm + tid * 4);
    float sum = v.x + v.y + v.z + v.w;
    sum = block_reduce_sum(sum, sb);
    float mu = sum * (1.f / Dm);
    float dx0 = v.x - mu, dx1 = v.y - mu, dx2 = v.z - mu, dx3 = v.w - mu;
    float ss = dx0 * dx0 + dx1 * dx1 + dx2 * dx2 + dx3 * dx3;
    ss = block_reduce_sum(ss, sb);
    float inv = rsqrtf(ss * (1.f / Dm) + 1e-5f);
    float4 gg = *(const float4*)(g + tid * 4);
    float4 bb = *(const float4*)(bta + tid * 4);
    v.x = dx0 * inv * gg.x + bb.x;
    v.y = dx1 * inv * gg.y + bb.y;
    v.z = dx2 * inv * gg.z + bb.z;
    v.w = dx3 * inv * gg.w + bb.w;
    *(float4*)(out + (size_t)t * Dm + tid * 4) = v;
}

// ---------------- host orchestration ----------------
static void launch_sgemm(const float* A, const float* B, float* C,
                         int M, int N, int K, int lda, int ldb, int ldc,
                         const float* bias, int epi) {
    dim3 grid((N + 127) / 128, M / 128);
    sgemm_kernel<<<grid, 256>>>(A, B, C, M, N, K, lda, ldb, ldc, bias, epi);
}

extern "C" void kernel_launch(void* const* d_in, const int* in_sizes, int n_in,
                              void* d_out, int out_size) {
    const int*   x      = (const int*)  d_in[0];
    const float* mask   = (const float*)d_in[1];
    const float* emb    = (const float*)d_in[2];
    const float* norm_w = (const float*)d_in[3];
    const float* W_in   = (const float*)d_in[4];
    const float* conv_w = (const float*)d_in[5];
    const float* conv_b = (const float*)d_in[6];
    const float* W_x    = (const float*)d_in[7];
    const float* W_dt   = (const float*)d_in[8];
    const float* b_dt   = (const float*)d_in[9];
    const float* A_log  = (const float*)d_in[10];
    const float* D_skip = (const float*)d_in[11];
    const float* W_out  = (const float*)d_in[12];
    const float* W_rw   = (const float*)d_in[13];
    const float* b_rw   = (const float*)d_in[14];
    const float* ln_g   = (const float*)d_in[15];
    const float* ln_b   = (const float*)d_in[16];
    const float* head_W = (const float*)d_in[17];
    float* out = (float*)d_out;

    float* base = nullptr;
    cudaGetSymbolAddress((void**)&base, g_scratch);
    float* gH     = base + OFF_H;
    float* gXN    = base + OFF_XN;
    float* gUZ    = base + OFF_UZ;
    float* gU     = base + OFF_U;
    float* gDBC   = base + OFF_DBC;
    float* gPART  = base + OFF_PART;
    float* gDELTA = base + OFF_DELTA;
    float* gY     = base + OFF_Y;
    float* gWBAR  = base + OFF_WBAR;
    float* gBSUM  = base + OFF_BSUM;

    // h = emb[x] * mask
    embed_kernel<<<Tn, 256>>>(x, mask, emb, gH);

    for (int lay = 0; lay < NLn; lay++) {
        const float* nw  = norm_w + (size_t)lay * Dm;
        const float* win = W_in   + (size_t)lay * Dm * 2 * Em;
        const float* cw  = conv_w + (size_t)lay * Em * Kc;
        const float* cb  = conv_b + (size_t)lay * Em;
        const float* wx  = W_x    + (size_t)lay * Em * RS2;
        const float* wdt = W_dt   + (size_t)lay * Rn * Em;
        const float* bdt = b_dt   + (size_t)lay * Em;
        const float* alg = A_log  + (size_t)lay * Em * Sn;
        const float* dsk = D_skip + (size_t)lay * Em;
        const float* wo  = W_out  + (size_t)lay * Em * Dm;
        const float* wrw = W_rw   + (size_t)lay * Dm * Sn;
        const float* brw = b_rw   + (size_t)lay * Sn;

        // xn = rmsnorm(h) * norm_w
        rmsnorm_kernel<<<Tn, 256>>>(gH, nw, gXN);
        // uz = xn @ W_in
        launch_sgemm(gXN, win, gUZ, Tn, 2 * Em, Dm, Dm, 2 * Em, 2 * Em, nullptr, 0);
        // u = silu(causal dwconv(uz[:, :E]))
        conv_silu_kernel<<<(Tn * Em) / 256, 256>>>(gUZ, cw, cb, gU);
        // dbc = u @ W_x  (split-K)
        {
            dim3 grid(Tn / 32, 8);
            dbc_gemm_kernel<<<grid, 96>>>(gU, wx, gPART);
            dbc_reduce_kernel<<<(Tn * RS2) / 256, 256>>>(gPART, gDBC);
        }
        // delta = softplus(dr @ W_dt + b_dt)   (dr = dbc[:, :64], lda = 96)
        launch_sgemm(gDBC, wdt, gDELTA, Tn, Em, Rn, RS2, Em, Em, bdt, 1);
        // y = selective_scan(u, delta, A, B, C, D_skip)
        scan_kernel<<<(Bn * Em * Sn) / 256, 256>>>(gDELTA, gU, gDBC, alg, dsk, gY);
        // y *= silu(z)
        gated_kernel<<<(Tn * Em) / 256, 256>>>(gUZ, gY);
        // h = h + y @ W_out
        launch_sgemm(gY, wo, gH, Tn, Dm, Em, Em, Dm, Dm, nullptr, 2);
        // h *= mean(h @ W_rw + b_rw)
        wbar_kernel<<<(Dm + 255) / 256, 256>>>(wrw, brw, gWBAR, gBSUM);
        rwscale_kernel<<<Tn, 256>>>(gH, gWBAR, gBSUM);
    }

    // final layernorm + head
    layernorm_kernel<<<Tn, 256>>>(gH, ln_g, ln_b, gXN);
    launch_sgemm(gXN, head_W, out, Tn, Vv, Dm, Dm, Vv, Vv, nullptr, 0);
}

// round 6
// speedup vs baseline: 2.1261x; 2.1261x over previous
#include <cuda_runtime.h>
#include <cuda_bf16.h>
#include <math.h>
#include <stdint.h>

// ---------------- problem constants ----------------
#define Bn   2
#define Ln   1024
#define Tn   2048      // B*L tokens
#define Dm   1024
#define Em   2048
#define Vv   32000
#define Sn   16
#define Rn   64
#define Kc   4
#define NLn  4
#define RS2  96        // R + 2S

// ---------------- fp32 scratch ----------------
static const size_t OFF_H     = 0;
static const size_t OFF_XN    = OFF_H     + (size_t)Tn*Dm;
static const size_t OFF_UZ    = OFF_XN    + (size_t)Tn*Dm;
static const size_t OFF_U     = OFF_UZ    + (size_t)Tn*2*Em;
static const size_t OFF_DBC   = OFF_U     + (size_t)Tn*Em;
static const size_t OFF_PART  = OFF_DBC   + (size_t)Tn*RS2;
static const size_t OFF_DELTA = OFF_PART  + (size_t)8*Tn*RS2;
static const size_t OFF_Y     = OFF_DELTA + (size_t)Tn*Em;
static const size_t OFF_WBAR  = OFF_Y     + (size_t)Tn*Em;
static const size_t OFF_BSUM  = OFF_WBAR  + (size_t)Dm;
static const size_t SCRATCH_TOTAL = OFF_BSUM + 16;

__device__ __align__(16) float g_scratch[SCRATCH_TOTAL];

// bf16 split buffers (hi/lo) for activations (A) and weights (B)
__device__ __align__(16) __nv_bfloat16 g_Ah[(size_t)Tn*Em];
__device__ __align__(16) __nv_bfloat16 g_Al[(size_t)Tn*Em];
__device__ __align__(16) __nv_bfloat16 g_Wh[(size_t)Dm*Vv];
__device__ __align__(16) __nv_bfloat16 g_Wl[(size_t)Dm*Vv];

// ---------------- helpers ----------------
__device__ __forceinline__ float block_reduce_sum(float v, float* sbuf) {
    #pragma unroll
    for (int o = 16; o; o >>= 1) v += __shfl_xor_sync(0xffffffffu, v, o);
    int w = threadIdx.x >> 5, ln = threadIdx.x & 31;
    if (ln == 0) sbuf[w] = v;
    __syncthreads();
    if (threadIdx.x < 32) {
        v = (threadIdx.x < (blockDim.x >> 5)) ? sbuf[threadIdx.x] : 0.f;
        #pragma unroll
        for (int o = 4; o; o >>= 1) v += __shfl_xor_sync(0xffffffffu, v, o);
        if (threadIdx.x == 0) sbuf[0] = v;
    }
    __syncthreads();
    float r = sbuf[0];
    __syncthreads();
    return r;
}

__device__ __forceinline__ float silu_f(float z) {
    return z / (1.f + __expf(-z));
}
__device__ __forceinline__ float softplus_f(float v) {
    return (v > 15.f) ? v : log1pf(__expf(v));
}

// ---------------- split fp32 -> bf16 hi/lo ----------------
__global__ void split_kernel(const float* __restrict__ src,
                             __nv_bfloat16* __restrict__ hi,
                             __nv_bfloat16* __restrict__ lo, int n4) {
    int i = blockIdx.x * blockDim.x + threadIdx.x;
    if (i >= n4) return;
    float4 v = ((const float4*)src)[i];
    __nv_bfloat16 h0 = __float2bfloat16_rn(v.x);
    __nv_bfloat16 h1 = __float2bfloat16_rn(v.y);
    __nv_bfloat16 h2 = __float2bfloat16_rn(v.z);
    __nv_bfloat16 h3 = __float2bfloat16_rn(v.w);
    __nv_bfloat16 l0 = __float2bfloat16_rn(v.x - __bfloat162float(h0));
    __nv_bfloat16 l1 = __float2bfloat16_rn(v.y - __bfloat162float(h1));
    __nv_bfloat16 l2 = __float2bfloat16_rn(v.z - __bfloat162float(h2));
    __nv_bfloat16 l3 = __float2bfloat16_rn(v.w - __bfloat162float(h3));
    uint2 ph, pl;
    ph.x = (uint32_t)__bfloat16_as_ushort(h0) | ((uint32_t)__bfloat16_as_ushort(h1) << 16);
    ph.y = (uint32_t)__bfloat16_as_ushort(h2) | ((uint32_t)__bfloat16_as_ushort(h3) << 16);
    pl.x = (uint32_t)__bfloat16_as_ushort(l0) | ((uint32_t)__bfloat16_as_ushort(l1) << 16);
    pl.y = (uint32_t)__bfloat16_as_ushort(l2) | ((uint32_t)__bfloat16_as_ushort(l3) << 16);
    ((uint2*)hi)[i] = ph;
    ((uint2*)lo)[i] = pl;
}

// ---------------- PTX wrappers ----------------
__device__ __forceinline__ void cp16(uint32_t s, const void* g) {
    asm volatile("cp.async.cg.shared.global [%0], [%1], 16;\n" :: "r"(s), "l"(g));
}
__device__ __forceinline__ void cp_commit() {
    asm volatile("cp.async.commit_group;\n");
}
__device__ __forceinline__ void ldsm_x4(uint32_t* r, uint32_t addr) {
    asm volatile("ldmatrix.sync.aligned.m8n8.x4.shared.b16 {%0,%1,%2,%3}, [%4];\n"
                 : "=r"(r[0]), "=r"(r[1]), "=r"(r[2]), "=r"(r[3]) : "r"(addr));
}
__device__ __forceinline__ void ldsm_x4_t(uint32_t* r, uint32_t addr) {
    asm volatile("ldmatrix.sync.aligned.m8n8.x4.trans.shared.b16 {%0,%1,%2,%3}, [%4];\n"
                 : "=r"(r[0]), "=r"(r[1]), "=r"(r[2]), "=r"(r[3]) : "r"(addr));
}
__device__ __forceinline__ void mma_bf16(float* d, const uint32_t* a, const uint32_t* b) {
    asm volatile("mma.sync.aligned.m16n8k16.row.col.f32.bf16.bf16.f32 "
                 "{%0,%1,%2,%3}, {%4,%5,%6,%7}, {%8,%9}, {%0,%1,%2,%3};\n"
                 : "+f"(d[0]), "+f"(d[1]), "+f"(d[2]), "+f"(d[3])
                 : "r"(a[0]), "r"(a[1]), "r"(a[2]), "r"(a[3]), "r"(b[0]), "r"(b[1]));
}

// ---------------- split-bf16 tensor-core GEMM ----------------
// C[MxN] = (Ah+Al)[MxK] * (Bh+Bl)[KxN], fp32 accum, 3 MMAs per product.
// epi 0: store; epi 1: softplus(acc + bias[n]); epi 2: C += acc
// requires: M%128==0, N%128==0, K%32==0, 16B-aligned rows (lda,ldb %8==0)
#define BM 128
#define BN 128
#define BKk 32
#define LDA_S 40
#define LDB_S 136
#define STAGE_BYTES (BM*LDA_S*2*2 + BKk*LDB_S*2*2)   // 20480 + 17408 = 37888
#define SMEM_GEMM (2*STAGE_BYTES)                    // 75776

__global__ __launch_bounds__(256) void bf16_gemm_kernel(
    const __nv_bfloat16* __restrict__ Ah, const __nv_bfloat16* __restrict__ Al,
    const __nv_bfloat16* __restrict__ Bh, const __nv_bfloat16* __restrict__ Bl,
    float* __restrict__ C, int M, int N, int Kd, int lda, int ldb, int ldc,
    const float* __restrict__ bias, int epi)
{
    extern __shared__ char sm[];
    const int tid = threadIdx.x, lane = tid & 31, warp = tid >> 5;
    const int bm = blockIdx.x * BM, bn = blockIdx.y * BN;
    const int wm = (warp >> 1) * 32, wn = (warp & 1) * 64;
    const uint32_t sbase = (uint32_t)__cvta_generic_to_shared(sm);

    float acc[2][8][4];
    #pragma unroll
    for (int a = 0; a < 2; a++)
        #pragma unroll
        for (int b = 0; b < 8; b++)
            #pragma unroll
            for (int c = 0; c < 4; c++) acc[a][b][c] = 0.f;

    // per-thread load coordinates
    const int a_r0 = (tid * 2) >> 2,      a_c0 = ((tid * 2) & 3) * 8;
    const int a_r1 = (tid * 2 + 1) >> 2,  a_c1 = ((tid * 2 + 1) & 3) * 8;
    const int b_r0 = (tid * 2) >> 4,      b_c0 = ((tid * 2) & 15) * 8;
    const int b_r1 = (tid * 2 + 1) >> 4,  b_c1 = ((tid * 2 + 1) & 15) * 8;

    auto load_stage = [&](int s, int k0) {
        uint32_t stA = sbase + (uint32_t)s * STAGE_BYTES;
        uint32_t stAl = stA + BM * LDA_S * 2;
        uint32_t stB = stA + BM * LDA_S * 4;
        uint32_t stBl = stB + BKk * LDB_S * 2;
        cp16(stA  + (uint32_t)(a_r0 * LDA_S + a_c0) * 2, Ah + (size_t)(bm + a_r0) * lda + k0 + a_c0);
        cp16(stA  + (uint32_t)(a_r1 * LDA_S + a_c1) * 2, Ah + (size_t)(bm + a_r1) * lda + k0 + a_c1);
        cp16(stAl + (uint32_t)(a_r0 * LDA_S + a_c0) * 2, Al + (size_t)(bm + a_r0) * lda + k0 + a_c0);
        cp16(stAl + (uint32_t)(a_r1 * LDA_S + a_c1) * 2, Al + (size_t)(bm + a_r1) * lda + k0 + a_c1);
        cp16(stB  + (uint32_t)(b_r0 * LDB_S + b_c0) * 2, Bh + (size_t)(k0 + b_r0) * ldb + bn + b_c0);
        cp16(stB  + (uint32_t)(b_r1 * LDB_S + b_c1) * 2, Bh + (size_t)(k0 + b_r1) * ldb + bn + b_c1);
        cp16(stBl + (uint32_t)(b_r0 * LDB_S + b_c0) * 2, Bl + (size_t)(k0 + b_r0) * ldb + bn + b_c0);
        cp16(stBl + (uint32_t)(b_r1 * LDB_S + b_c1) * 2, Bl + (size_t)(k0 + b_r1) * ldb + bn + b_c1);
    };

    const int niter = Kd / BKk;
    load_stage(0, 0);
    cp_commit();

    for (int it = 0; it < niter; it++) {
        const int s = it & 1;
        if (it + 1 < niter) {
            load_stage(s ^ 1, (it + 1) * BKk);
            cp_commit();
            asm volatile("cp.async.wait_group 1;\n");
        } else {
            asm volatile("cp.async.wait_group 0;\n");
        }
        __syncthreads();

        const uint32_t stA = sbase + (uint32_t)s * STAGE_BYTES;
        const uint32_t stAl = stA + BM * LDA_S * 2;
        const uint32_t stB = stA + BM * LDA_S * 4;
        const uint32_t stBl = stB + BKk * LDB_S * 2;

        #pragma unroll
        for (int kk = 0; kk < BKk; kk += 16) {
            uint32_t ah[2][4], al[2][4], bh[4][4], bl[4][4];
            #pragma unroll
            for (int mi = 0; mi < 2; mi++) {
                uint32_t ao = (uint32_t)((wm + mi * 16 + (lane & 15)) * LDA_S + kk + (lane >> 4) * 8) * 2;
                ldsm_x4(ah[mi], stA + ao);
                ldsm_x4(al[mi], stAl + ao);
            }
            #pragma unroll
            for (int j = 0; j < 4; j++) {
                uint32_t bo = (uint32_t)((kk + (lane & 15)) * LDB_S + wn + j * 16 + (lane >> 4) * 8) * 2;
                ldsm_x4_t(bh[j], stB + bo);
                ldsm_x4_t(bl[j], stBl + bo);
            }
            #pragma unroll
            for (int mi = 0; mi < 2; mi++)
                #pragma unroll
                for (int j = 0; j < 4; j++)
                    #pragma unroll
                    for (int h2 = 0; h2 < 2; h2++) {
                        const int nj = j * 2 + h2;
                        mma_bf16(acc[mi][nj], ah[mi], &bh[j][h2 * 2]);
                        mma_bf16(acc[mi][nj], ah[mi], &bl[j][h2 * 2]);
                        mma_bf16(acc[mi][nj], al[mi], &bh[j][h2 * 2]);
                    }
        }
        __syncthreads();
    }

    // epilogue
    #pragma unroll
    for (int mi = 0; mi < 2; mi++)
        #pragma unroll
        for (int nj = 0; nj < 8; nj++) {
            int row0 = bm + wm + mi * 16 + (lane >> 2);
            int col = bn + wn + nj * 8 + (lane & 3) * 2;
            float a0 = acc[mi][nj][0], a1 = acc[mi][nj][1];
            float a2 = acc[mi][nj][2], a3 = acc[mi][nj][3];
            float* p0 = C + (size_t)row0 * ldc + col;
            float* p1 = C + (size_t)(row0 + 8) * ldc + col;
            if (epi == 0) {
                p0[0] = a0; p0[1] = a1; p1[0] = a2; p1[1] = a3;
            } else if (epi == 1) {
                float b0 = bias[col], b1 = bias[col + 1];
                p0[0] = softplus_f(a0 + b0); p0[1] = softplus_f(a1 + b1);
                p1[0] = softplus_f(a2 + b0); p1[1] = softplus_f(a3 + b1);
            } else {
                p0[0] += a0; p0[1] += a1; p1[0] += a2; p1[1] += a3;
            }
        }
}

// ---------------- embedding gather ----------------
__global__ void embed_kernel(const int* __restrict__ x, const float* __restrict__ mask,
                             const float* __restrict__ emb, float* __restrict__ h) {
    int t = blockIdx.x;
    int tid = threadIdx.x;
    int tok = x[t];
    float m = mask[t];
    float4 v = *(const float4*)(emb + (size_t)tok * Dm + tid * 4);
    v.x *= m; v.y *= m; v.z *= m; v.w *= m;
    *(float4*)(h + (size_t)t * Dm + tid * 4) = v;
}

// ---------------- RMSNorm ----------------
__global__ void rmsnorm_kernel(const float* __restrict__ h, const float* __restrict__ nw,
                               float* __restrict__ xn) {
    __shared__ float sb[32];
    int t = blockIdx.x, tid = threadIdx.x;
    float4 v = *(const float4*)(h + (size_t)t * Dm + tid * 4);
    float ss = v.x*v.x + v.y*v.y + v.z*v.z + v.w*v.w;
    ss = block_reduce_sum(ss, sb);
    float sc = rsqrtf(ss * (1.f / Dm) + 1e-5f);
    float4 w = *(const float4*)(nw + tid * 4);
    v.x = v.x * sc * w.x; v.y = v.y * sc * w.y;
    v.z = v.z * sc * w.z; v.w = v.w * sc * w.w;
    *(float4*)(xn + (size_t)t * Dm + tid * 4) = v;
}

// ---------------- causal depthwise conv (K=4) + SiLU ----------------
__global__ void conv_silu_kernel(const float* __restrict__ uz, const float* __restrict__ cw,
                                 const float* __restrict__ cb, float* __restrict__ u) {
    int idx = blockIdx.x * blockDim.x + threadIdx.x;
    int e = idx & (Em - 1);
    int t = idx >> 11;
    int l = t & (Ln - 1);
    float acc = cb[e];
    #pragma unroll
    for (int k = 0; k < Kc; k++) {
        int li = l - (Kc - 1) + k;
        if (li >= 0)
            acc = fmaf(uz[(size_t)(t - (Kc - 1) + k) * (2 * Em) + e], cw[e * Kc + k], acc);
    }
    u[idx] = silu_f(acc);
}

// ---------------- dbc = u @ W_x (tall-skinny, split-K, fp32) ----------------
__global__ void dbc_gemm_kernel(const float* __restrict__ U, const float* __restrict__ Wx,
                                float* __restrict__ part) {
    __shared__ float su[32][33];
    const int n = threadIdx.x;
    const int t0 = blockIdx.x * 32;
    const int k0 = blockIdx.y * (Em / 8);
    float acc[32];
    #pragma unroll
    for (int t = 0; t < 32; t++) acc[t] = 0.f;

    for (int kc = 0; kc < Em / 8; kc += 32) {
        for (int i = n; i < 32 * 32; i += 96) {
            int t = i >> 5, kk = i & 31;
            su[t][kk] = U[(size_t)(t0 + t) * Em + k0 + kc + kk];
        }
        __syncthreads();
        for (int kk = 0; kk < 32; kk++) {
            float w = Wx[(size_t)(k0 + kc + kk) * RS2 + n];
            #pragma unroll
            for (int t = 0; t < 32; t++)
                acc[t] = fmaf(su[t][kk], w, acc[t]);
        }
        __syncthreads();
    }
    #pragma unroll
    for (int t = 0; t < 32; t++)
        part[((size_t)blockIdx.y * Tn + (t0 + t)) * RS2 + n] = acc[t];
}

__global__ void dbc_reduce_kernel(const float* __restrict__ part, float* __restrict__ dbc) {
    int idx = blockIdx.x * blockDim.x + threadIdx.x;
    float s = 0.f;
    #pragma unroll
    for (int j = 0; j < 8; j++) s += part[(size_t)j * Tn * RS2 + idx];
    dbc[idx] = s;
}

// ---------------- selective scan ----------------
__global__ void scan_kernel(const float* __restrict__ delta, const float* __restrict__ u,
                            const float* __restrict__ dbc, const float* __restrict__ A_log,
                            const float* __restrict__ Dskip, float* __restrict__ y) {
    int tid = blockIdx.x * blockDim.x + threadIdx.x;
    int s = tid & (Sn - 1);
    int e = (tid >> 4) & (Em - 1);
    int b = tid >> 15;
    float Aes = -__expf(A_log[e * Sn + s]);
    float dsk = Dskip[e];
    float h = 0.f;
    int t = b * Ln;
    for (int l = 0; l < Ln; l++, t++) {
        float dlt = delta[(size_t)t * Em + e];
        float uu  = u[(size_t)t * Em + e];
        float Bv  = dbc[(size_t)t * RS2 + Rn + s];
        float Cv  = dbc[(size_t)t * RS2 + Rn + Sn + s];
        float dA = __expf(dlt * Aes);
        h = fmaf(dA, h, dlt * uu * Bv);
        float c = h * Cv;
        c += __shfl_xor_sync(0xffffffffu, c, 1);
        c += __shfl_xor_sync(0xffffffffu, c, 2);
        c += __shfl_xor_sync(0xffffffffu, c, 4);
        c += __shfl_xor_sync(0xffffffffu, c, 8);
        if (s == 0) y[(size_t)t * Em + e] = fmaf(uu, dsk, c);
    }
}

// ---------------- gated = y * silu(z) ----------------
__global__ void gated_kernel(const float* __restrict__ uz, float* __restrict__ y) {
    int idx = blockIdx.x * blockDim.x + threadIdx.x;
    int e = idx & (Em - 1);
    int t = idx >> 11;
    float z = uz[(size_t)t * (2 * Em) + Em + e];
    y[idx] *= silu_f(z);
}

// ---------------- rw mean scale (folded GEMM) ----------------
__global__ void wbar_kernel(const float* __restrict__ Wrw, const float* __restrict__ brw,
                            float* __restrict__ wbar, float* __restrict__ bsum) {
    int d = blockIdx.x * blockDim.x + threadIdx.x;
    if (d < Dm) {
        float s = 0.f;
        #pragma unroll
        for (int j = 0; j < Sn; j++) s += Wrw[(size_t)d * Sn + j];
        wbar[d] = s;
    }
    if (d == 0) {
        float s = 0.f;
        #pragma unroll
        for (int j = 0; j < Sn; j++) s += brw[j];
        *bsum = s;
    }
}

__global__ void rwscale_kernel(float* __restrict__ h, const float* __restrict__ wbar,
                               const float* __restrict__ bsum) {
    __shared__ float sb[32];
    int t = blockIdx.x, tid = threadIdx.x;
    float4 v = *(const float4*)(h + (size_t)t * Dm + tid * 4);
    float4 w = *(const float4*)(wbar + tid * 4);
    float dot = v.x * w.x + v.y * w.y + v.z * w.z + v.w * w.w;
    dot = block_reduce_sum(dot, sb);
    float val = (dot + *bsum) * (1.f / Sn);
    v.x *= val; v.y *= val; v.z *= val; v.w *= val;
    *(float4*)(h + (size_t)t * Dm + tid * 4) = v;
}

// ---------------- final LayerNorm ----------------
__global__ void layernorm_kernel(const float* __restrict__ h, const float* __restrict__ g,
                                 const float* __restrict__ bta, float* __restrict__ out) {
    __shared__ float sb[32];
    int t = blockIdx.x, tid = threadIdx.x;
    float4 v = *(const float4*)(h + (size_t)t * Dm + tid * 4);
    float sum = v.x + v.y + v.z + v.w;
    sum = block_reduce_sum(sum, sb);
    float mu = sum * (1.f / Dm);
    float dx0 = v.x - mu, dx1 = v.y - mu, dx2 = v.z - mu, dx3 = v.w - mu;
    float ss = dx0 * dx0 + dx1 * dx1 + dx2 * dx2 + dx3 * dx3;
    ss = block_reduce_sum(ss, sb);
    float inv = rsqrtf(ss * (1.f / Dm) + 1e-5f);
    float4 gg = *(const float4*)(g + tid * 4);
    float4 bb = *(const float4*)(bta + tid * 4);
    v.x = dx0 * inv * gg.x + bb.x;
    v.y = dx1 * inv * gg.y + bb.y;
    v.z = dx2 * inv * gg.z + bb.z;
    v.w = dx3 * inv * gg.w + bb.w;
    *(float4*)(out + (size_t)t * Dm + tid * 4) = v;
}

// ---------------- host orchestration ----------------
static void launch_split(const float* src, __nv_bfloat16* hi, __nv_bfloat16* lo, size_t n) {
    int n4 = (int)(n / 4);
    split_kernel<<<(n4 + 255) / 256, 256>>>(src, hi, lo, n4);
}

static void launch_bf16_gemm(const __nv_bfloat16* Ah, const __nv_bfloat16* Al,
                             const __nv_bfloat16* Bh, const __nv_bfloat16* Bl,
                             float* C, int M, int N, int K,
                             int lda, int ldb, int ldc,
                             const float* bias, int epi) {
    cudaFuncSetAttribute(bf16_gemm_kernel, cudaFuncAttributeMaxDynamicSharedMemorySize, SMEM_GEMM);
    dim3 grid(M / BM, N / BN);
    bf16_gemm_kernel<<<grid, 256, SMEM_GEMM>>>(Ah, Al, Bh, Bl, C, M, N, K, lda, ldb, ldc, bias, epi);
}

extern "C" void kernel_launch(void* const* d_in, const int* in_sizes, int n_in,
                              void* d_out, int out_size) {
    const int*   x      = (const int*)  d_in[0];
    const float* mask   = (const float*)d_in[1];
    const float* emb    = (const float*)d_in[2];
    const float* norm_w = (const float*)d_in[3];
    const float* W_in   = (const float*)d_in[4];
    const float* conv_w = (const float*)d_in[5];
    const float* conv_b = (const float*)d_in[6];
    const float* W_x    = (const float*)d_in[7];
    const float* W_dt   = (const float*)d_in[8];
    const float* b_dt   = (const float*)d_in[9];
    const float* A_log  = (const float*)d_in[10];
    const float* D_skip = (const float*)d_in[11];
    const float* W_out  = (const float*)d_in[12];
    const float* W_rw   = (const float*)d_in[13];
    const float* b_rw   = (const float*)d_in[14];
    const float* ln_g   = (const float*)d_in[15];
    const float* ln_b   = (const float*)d_in[16];
    const float* head_W = (const float*)d_in[17];
    float* out = (float*)d_out;

    float* base = nullptr;
    cudaGetSymbolAddress((void**)&base, g_scratch);
    float* gH     = base + OFF_H;
    float* gXN    = base + OFF_XN;
    float* gUZ    = base + OFF_UZ;
    float* gU     = base + OFF_U;
    float* gDBC   = base + OFF_DBC;
    float* gPART  = base + OFF_PART;
    float* gDELTA = base + OFF_DELTA;
    float* gY     = base + OFF_Y;
    float* gWBAR  = base + OFF_WBAR;
    float* gBSUM  = base + OFF_BSUM;

    __nv_bfloat16 *gAh = nullptr, *gAl = nullptr, *gWh = nullptr, *gWl = nullptr;
    cudaGetSymbolAddress((void**)&gAh, g_Ah);
    cudaGetSymbolAddress((void**)&gAl, g_Al);
    cudaGetSymbolAddress((void**)&gWh, g_Wh);
    cudaGetSymbolAddress((void**)&gWl, g_Wl);

    // h = emb[x] * mask
    embed_kernel<<<Tn, 256>>>(x, mask, emb, gH);

    for (int lay = 0; lay < NLn; lay++) {
        const float* nw  = norm_w + (size_t)lay * Dm;
        const float* win = W_in   + (size_t)lay * Dm * 2 * Em;
        const float* cw  = conv_w + (size_t)lay * Em * Kc;
        const float* cb  = conv_b + (size_t)lay * Em;
        const float* wx  = W_x    + (size_t)lay * Em * RS2;
        const float* wdt = W_dt   + (size_t)lay * Rn * Em;
        const float* bdt = b_dt   + (size_t)lay * Em;
        const float* alg = A_log  + (size_t)lay * Em * Sn;
        const float* dsk = D_skip + (size_t)lay * Em;
        const float* wo  = W_out  + (size_t)lay * Em * Dm;
        const float* wrw = W_rw   + (size_t)lay * Dm * Sn;
        const float* brw = b_rw   + (size_t)lay * Sn;

        // xn = rmsnorm(h) * norm_w
        rmsnorm_kernel<<<Tn, 256>>>(gH, nw, gXN);
        // uz = xn @ W_in  (tensor core, split bf16)
        launch_split(gXN, gAh, gAl, (size_t)Tn * Dm);
        launch_split(win, gWh, gWl, (size_t)Dm * 2 * Em);
        launch_bf16_gemm(gAh, gAl, gWh, gWl, gUZ, Tn, 2 * Em, Dm, Dm, 2 * Em, 2 * Em, nullptr, 0);
        // u = silu(causal dwconv(uz[:, :E]))
        conv_silu_kernel<<<(Tn * Em) / 256, 256>>>(gUZ, cw, cb, gU);
        // dbc = u @ W_x  (split-K fp32; tiny)
        {
            dim3 grid(Tn / 32, 8);
            dbc_gemm_kernel<<<grid, 96>>>(gU, wx, gPART);
            dbc_reduce_kernel<<<(Tn * RS2) / 256, 256>>>(gPART, gDBC);
        }
        // delta = softplus(dbc[:, :64] @ W_dt + b_dt)
        launch_split(gDBC, gAh, gAl, (size_t)Tn * RS2);
        launch_split(wdt, gWh, gWl, (size_t)Rn * Em);
        launch_bf16_gemm(gAh, gAl, gWh, gWl, gDELTA, Tn, Em, Rn, RS2, Em, Em, bdt, 1);
        // y = selective_scan(...)
        scan_kernel<<<(Bn * Em * Sn) / 256, 256>>>(gDELTA, gU, gDBC, alg, dsk, gY);
        // y *= silu(z)
        gated_kernel<<<(Tn * Em) / 256, 256>>>(gUZ, gY);
        // h = h + y @ W_out  (tensor core)
        launch_split(gY, gAh, gAl, (size_t)Tn * Em);
        launch_split(wo, gWh, gWl, (size_t)Em * Dm);
        launch_bf16_gemm(gAh, gAl, gWh, gWl, gH, Tn, Dm, Em, Em, Dm, Dm, nullptr, 2);
        // h *= mean(h @ W_rw + b_rw)  (folded)
        wbar_kernel<<<(Dm + 255) / 256, 256>>>(wrw, brw, gWBAR, gBSUM);
        rwscale_kernel<<<Tn, 256>>>(gH, gWBAR, gBSUM);
    }

    // final layernorm + head (tensor core)
    layernorm_kernel<<<Tn, 256>>>(gH, ln_g, ln_b, gXN);
    launch_split(gXN, gAh, gAl, (size_t)Tn * Dm);
    launch_split(head_W, gWh, gWl, (size_t)Dm * Vv);
    launch_bf16_gemm(gAh, gAl, gWh, gWl, out, Tn, Vv, Dm, Dm, Vv, Vv, nullptr, 0);
}